// round 1
// baseline (speedup 1.0000x reference)
#include <cuda_runtime.h>
#include <cuda_bf16.h>
#include <cstdint>

// ---------------- Problem constants ----------------
#define BSZ     4
#define LSEQ    2048
#define DM      1024
#define DI      2048
#define DS      16
#define MROWS   (BSZ*LSEQ)      // 8192
#define NXZ     (2*DI)          // 4096
#define NDBL    (1 + 2*DS)      // 33

// ---------------- Scratch (device globals; no allocation allowed) ----------------
__device__ float g_xz[(size_t)MROWS * NXZ];     // 128 MB : [row][0..2047]=xc, [2048..4095]=z
__device__ float g_xs[(size_t)MROWS * DI];      // 64 MB  : silu(conv(xc))
__device__ float g_dbl[(size_t)MROWS * NDBL];   // ~1 MB  : [draw | B(16) | C(16)]
__device__ float g_delta[(size_t)MROWS * DI];   // 64 MB  : softplus(draw*w_dt+b_dt)
__device__ float g_y[(size_t)MROWS * DI];       // 64 MB  : gated scan output

// ---------------- fast math helpers ----------------
__device__ __forceinline__ float ex2a(float x) { float r; asm("ex2.approx.f32 %0, %1;" : "=f"(r) : "f"(x)); return r; }
__device__ __forceinline__ float lg2a(float x) { float r; asm("lg2.approx.f32 %0, %1;" : "=f"(r) : "f"(x)); return r; }
__device__ __forceinline__ float rcpa(float x) { float r; asm("rcp.approx.f32 %0, %1;" : "=f"(r) : "f"(x)); return r; }
#define LOG2E 1.44269504088896340736f
#define LN2   0.69314718055994530942f

__device__ __forceinline__ float silu_f(float v) {
    return v * rcpa(1.f + ex2a(-LOG2E * v));
}

// ---------------- SGEMM: C[M,N] = A[M,K] @ B[K,N], all row-major ----------------
// 128x128 block tile, BK=16, 256 threads, 8x8 per-thread tile, double-buffered SMEM.
// Requires M%128==0, N%128==0, K%16==0 (true for both call sites).
template<int M, int N, int K>
__device__ __forceinline__ void sgemm_body(
    const float* __restrict__ A, const float* __restrict__ B, float* __restrict__ C)
{
    constexpr int BM = 128, BN = 128, BK = 16;
    __shared__ float As[2][BK][BM + 4];
    __shared__ float Bs[2][BK][BN + 4];

    const int tid = threadIdx.x;
    const int m0 = blockIdx.y * BM;
    const int n0 = blockIdx.x * BN;
    const int tx = tid & 15;     // n-direction
    const int ty = tid >> 4;     // m-direction

    // A tile load map: 128x16 floats as 512 float4; 2 per thread
    const int ar0 = tid >> 2;            // 0..63
    const int ar1 = ar0 + 64;            // 64..127
    const int akc = (tid & 3) * 4;       // 0,4,8,12
    // B tile load map: 16x128 floats as 512 float4; 2 per thread
    const int br0 = tid >> 5;            // 0..7
    const int br1 = br0 + 8;             // 8..15
    const int bnc = (tid & 31) * 4;      // 0..124

    const float* Ab = A + (size_t)m0 * K;
    const float* Bb = B + n0;

    float acc[8][8];
    #pragma unroll
    for (int i = 0; i < 8; ++i)
        #pragma unroll
        for (int j = 0; j < 8; ++j) acc[i][j] = 0.f;

    float4 pa0 = *(const float4*)(Ab + (size_t)ar0 * K + akc);
    float4 pa1 = *(const float4*)(Ab + (size_t)ar1 * K + akc);
    float4 pb0 = *(const float4*)(Bb + (size_t)br0 * N + bnc);
    float4 pb1 = *(const float4*)(Bb + (size_t)br1 * N + bnc);

    int buf = 0;
    As[0][akc+0][ar0] = pa0.x; As[0][akc+1][ar0] = pa0.y; As[0][akc+2][ar0] = pa0.z; As[0][akc+3][ar0] = pa0.w;
    As[0][akc+0][ar1] = pa1.x; As[0][akc+1][ar1] = pa1.y; As[0][akc+2][ar1] = pa1.z; As[0][akc+3][ar1] = pa1.w;
    *(float4*)(&Bs[0][br0][bnc]) = pb0;
    *(float4*)(&Bs[0][br1][bnc]) = pb1;
    __syncthreads();

    for (int k0 = BK; k0 < K + BK; k0 += BK) {
        const bool more = (k0 < K);
        if (more) {
            pa0 = *(const float4*)(Ab + (size_t)ar0 * K + k0 + akc);
            pa1 = *(const float4*)(Ab + (size_t)ar1 * K + k0 + akc);
            pb0 = *(const float4*)(Bb + (size_t)(k0 + br0) * N + bnc);
            pb1 = *(const float4*)(Bb + (size_t)(k0 + br1) * N + bnc);
        }
        #pragma unroll
        for (int k = 0; k < BK; ++k) {
            float av[8], bv[8];
            *(float4*)&av[0] = *(const float4*)(&As[buf][k][ty * 8]);
            *(float4*)&av[4] = *(const float4*)(&As[buf][k][ty * 8 + 4]);
            *(float4*)&bv[0] = *(const float4*)(&Bs[buf][k][tx * 8]);
            *(float4*)&bv[4] = *(const float4*)(&Bs[buf][k][tx * 8 + 4]);
            #pragma unroll
            for (int i = 0; i < 8; ++i)
                #pragma unroll
                for (int j = 0; j < 8; ++j)
                    acc[i][j] = fmaf(av[i], bv[j], acc[i][j]);
        }
        if (more) {
            buf ^= 1;
            As[buf][akc+0][ar0] = pa0.x; As[buf][akc+1][ar0] = pa0.y; As[buf][akc+2][ar0] = pa0.z; As[buf][akc+3][ar0] = pa0.w;
            As[buf][akc+0][ar1] = pa1.x; As[buf][akc+1][ar1] = pa1.y; As[buf][akc+2][ar1] = pa1.z; As[buf][akc+3][ar1] = pa1.w;
            *(float4*)(&Bs[buf][br0][bnc]) = pb0;
            *(float4*)(&Bs[buf][br1][bnc]) = pb1;
            __syncthreads();
        }
    }

    #pragma unroll
    for (int i = 0; i < 8; ++i) {
        float* cp = C + (size_t)(m0 + ty * 8 + i) * N + n0 + tx * 8;
        *(float4*)(cp)     = make_float4(acc[i][0], acc[i][1], acc[i][2], acc[i][3]);
        *(float4*)(cp + 4) = make_float4(acc[i][4], acc[i][5], acc[i][6], acc[i][7]);
    }
}

__global__ __launch_bounds__(256) void gemm_in_kernel(
    const float* __restrict__ x, const float* __restrict__ W_in)
{
    sgemm_body<MROWS, NXZ, DM>(x, W_in, g_xz);
}

__global__ __launch_bounds__(256) void gemm_out_kernel(
    const float* __restrict__ W_out, float* __restrict__ out)
{
    sgemm_body<MROWS, DM, DI>(g_y, W_out, out);
}

// ---------------- depthwise causal conv (D_CONV=4) + SiLU ----------------
// xconv[b,l,d] = conv_b[d] + sum_{k=0..3} xc[b, l-3+k, d] * conv_w[d,k]
__global__ __launch_bounds__(256) void conv_silu_kernel(
    const float* __restrict__ conv_w, const float* __restrict__ conv_b)
{
    const int d  = blockIdx.x * 256 + threadIdx.x;   // grid.x = DI/256 = 8
    const int l0 = blockIdx.y * 128;                 // grid.y = LSEQ/128 = 16
    const int b  = blockIdx.z;                       // grid.z = BSZ

    const float w0 = conv_w[d * 4 + 0];
    const float w1 = conv_w[d * 4 + 1];
    const float w2 = conv_w[d * 4 + 2];
    const float w3 = conv_w[d * 4 + 3];
    const float bias = conv_b[d];

    const float* base = g_xz + ((size_t)b * LSEQ) * NXZ + d;   // xc column d
    float xm3 = (l0 >= 3) ? base[(size_t)(l0 - 3) * NXZ] : 0.f;
    float xm2 = (l0 >= 2) ? base[(size_t)(l0 - 2) * NXZ] : 0.f;
    float xm1 = (l0 >= 1) ? base[(size_t)(l0 - 1) * NXZ] : 0.f;

    float* outp = g_xs + ((size_t)b * LSEQ + l0) * DI + d;
    #pragma unroll 4
    for (int i = 0; i < 128; ++i) {
        float xl = base[(size_t)(l0 + i) * NXZ];
        float v = bias + w0 * xm3 + w1 * xm2 + w2 * xm1 + w3 * xl;
        outp[(size_t)i * DI] = silu_f(v);
        xm3 = xm2; xm2 = xm1; xm1 = xl;
    }
}

// ---------------- x_dbl = xs @ W_x  (N=33) ----------------
// 64 rows per block, 128 threads: thread = (row r, col-half jh). acc in registers.
__global__ __launch_bounds__(128) void dbl_kernel(const float* __restrict__ W_x)
{
    __shared__ float xs_s[64][33];
    __shared__ float wx_s[32][33];
    const int tid = threadIdx.x;
    const int r = tid & 63;
    const int jh = tid >> 6;            // 0 -> j 0..16, 1 -> j 17..32
    const int rows0 = blockIdx.x * 64;  // grid = 8192/64 = 128

    float acc[17];
    #pragma unroll
    for (int jj = 0; jj < 17; ++jj) acc[jj] = 0.f;

    for (int kt = 0; kt < DI; kt += 32) {
        __syncthreads();
        #pragma unroll
        for (int i = 0; i < 16; ++i) {
            int id = tid + i * 128;           // 0..2047
            int rr = id >> 5, kk = id & 31;
            xs_s[rr][kk] = g_xs[(size_t)(rows0 + rr) * DI + kt + kk];
        }
        for (int idx = tid; idx < 32 * 33; idx += 128) {
            int kk = idx / 33, j = idx % 33;
            wx_s[kk][j] = W_x[(size_t)(kt + kk) * NDBL + j];
        }
        __syncthreads();
        #pragma unroll
        for (int k = 0; k < 32; ++k) {
            float xv = xs_s[r][k];
            const float* wrow = &wx_s[k][jh * 17];
            #pragma unroll
            for (int jj = 0; jj < 16; ++jj)
                acc[jj] = fmaf(xv, wrow[jj], acc[jj]);
            if (jh == 0)
                acc[16] = fmaf(xv, wrow[16], acc[16]);
        }
    }
    const int nj = 17 - jh;
    const int jbase = jh * 17;
    for (int jj = 0; jj < nj; ++jj)
        g_dbl[(size_t)(rows0 + r) * NDBL + jbase + jj] = acc[jj];
}

// ---------------- delta = softplus(draw * w_dt + b_dt), fully parallel ----------------
__global__ __launch_bounds__(256) void delta_kernel(
    const float* __restrict__ w_dt, const float* __restrict__ b_dt)
{
    const int d = blockIdx.x * 256 + threadIdx.x;   // grid.x = 8
    const int row = blockIdx.y;                     // grid.y = 8192
    float draw = g_dbl[(size_t)row * NDBL];         // broadcast within block
    float xv = fmaf(draw, w_dt[d], b_dt[d]);
    float t = ex2a(-LOG2E * fabsf(xv));
    float sp = fmaxf(xv, 0.f) + LN2 * lg2a(1.f + t);
    g_delta[(size_t)row * DI + d] = sp;
}

// ---------------- selective scan + output gating ----------------
// Block: 128 threads = 64 channels (2 lanes per channel; 8 states per lane).
// Grid: (DI/64 = 32, BSZ = 4). B/C staged in SMEM in chunks of 32 timesteps.
__global__ __launch_bounds__(128) void scan_kernel(
    const float* __restrict__ A_log, const float* __restrict__ Dw)
{
    const int b = blockIdx.y;
    const int d0 = blockIdx.x * 64;
    const int tid = threadIdx.x;
    const int ch = tid >> 1;
    const int half = tid & 1;
    const int d = d0 + ch;
    const int row0 = b * LSEQ;

    // cn[j] = A[d][n] * log2(e),  n = half*8 + j ; A = -exp(A_log)
    float cn[8];
    #pragma unroll
    for (int j = 0; j < 8; ++j)
        cn[j] = -__expf(A_log[(size_t)d * DS + half * 8 + j]) * LOG2E;
    const float Dv = Dw[d];

    float h[8];
    #pragma unroll
    for (int j = 0; j < 8; ++j) h[j] = 0.f;

    __shared__ float sB[32][16];
    __shared__ float sC[32][16];

    for (int lc = 0; lc < LSEQ; lc += 32) {
        __syncthreads();
        // stage B,C for 32 steps: 1024 floats, 8 per thread
        #pragma unroll
        for (int i = 0; i < 8; ++i) {
            int id = tid + i * 128;        // 0..1023
            int ll = id >> 5;              // timestep in chunk
            int cc = id & 31;              // 0..31
            float v = g_dbl[(size_t)(row0 + lc + ll) * NDBL + 1 + cc];
            if (cc < 16) sB[ll][cc] = v; else sC[ll][cc - 16] = v;
        }
        __syncthreads();

        for (int i = 0; i < 32; ++i) {
            const int l = lc + i;
            const size_t idx = (size_t)(row0 + l) * DI + d;
            float dt = g_delta[idx];
            float xv = g_xs[idx];
            float dtx = dt * xv;
            float yacc = 0.f;
            const float* bp = &sB[i][half * 8];
            const float* cp = &sC[i][half * 8];
            #pragma unroll
            for (int j = 0; j < 8; ++j) {
                float a = ex2a(dt * cn[j]);
                float t = dtx * bp[j];
                h[j] = fmaf(a, h[j], t);
                yacc = fmaf(h[j], cp[j], yacc);
            }
            yacc += __shfl_xor_sync(0xffffffffu, yacc, 1);
            if (half == 0) {
                float zv = g_xz[(size_t)(row0 + l) * NXZ + DI + d];
                float out = (yacc + xv * Dv) * silu_f(zv);
                g_y[idx] = out;
            }
        }
    }
}

// ---------------- launch ----------------
extern "C" void kernel_launch(void* const* d_in, const int* in_sizes, int n_in,
                              void* d_out, int out_size)
{
    const float* x      = (const float*)d_in[0];
    const float* W_in   = (const float*)d_in[1];
    const float* conv_w = (const float*)d_in[2];
    const float* conv_b = (const float*)d_in[3];
    const float* W_x    = (const float*)d_in[4];
    const float* w_dt   = (const float*)d_in[5];
    const float* b_dt   = (const float*)d_in[6];
    const float* A_log  = (const float*)d_in[7];
    const float* Dw     = (const float*)d_in[8];
    const float* W_out  = (const float*)d_in[9];
    float* out = (float*)d_out;

    // 1) xz = x @ W_in            (8192x1024 @ 1024x4096)
    gemm_in_kernel<<<dim3(NXZ / 128, MROWS / 128), 256>>>(x, W_in);
    // 2) xs = silu(conv(xc))
    conv_silu_kernel<<<dim3(DI / 256, LSEQ / 128, BSZ), 256>>>(conv_w, conv_b);
    // 3) x_dbl = xs @ W_x         (N=33)
    dbl_kernel<<<MROWS / 64, 128>>>(W_x);
    // 4) delta = softplus(draw * w_dt + b_dt)
    delta_kernel<<<dim3(DI / 256, MROWS), 256>>>(w_dt, b_dt);
    // 5) selective scan + gating -> g_y
    scan_kernel<<<dim3(DI / 64, BSZ), 128>>>(A_log, Dw);
    // 6) out = y @ W_out          (8192x2048 @ 2048x1024)
    gemm_out_kernel<<<dim3(DM / 128, MROWS / 128), 256>>>(W_out, out);
}

// round 3
// speedup vs baseline: 1.1983x; 1.1983x over previous
#include <cuda_runtime.h>
#include <cuda_bf16.h>
#include <mma.h>
#include <cstdint>

using namespace nvcuda;

// ---------------- Problem constants ----------------
#define BSZ     4
#define LSEQ    2048
#define DM      1024
#define DI      2048
#define DS      16
#define MROWS   (BSZ*LSEQ)      // 8192
#define NXZ     (2*DI)          // 4096
#define NDBL    (1 + 2*DS)      // 33

// ---------------- Scratch (device globals; no allocation allowed) ----------------
__device__ float g_xz[(size_t)MROWS * NXZ];          // [row][0..2047]=xc, [2048..4095]=z
__device__ float g_xs[(size_t)MROWS * DI];           // silu(conv(xc))
__device__ float g_dbl[(size_t)MROWS * NDBL];        // [draw | B(16) | C(16)]
__device__ float g_delta[(size_t)MROWS * DI];        // softplus(draw*w_dt+b_dt)

__device__ __nv_bfloat16 g_xhi[(size_t)MROWS * DM];      // x hi/lo (GEMM1 A)
__device__ __nv_bfloat16 g_xlo[(size_t)MROWS * DM];
__device__ __nv_bfloat16 g_winT_hi[(size_t)NXZ * DM];    // W_in^T [4096][1024]
__device__ __nv_bfloat16 g_winT_lo[(size_t)NXZ * DM];
__device__ __nv_bfloat16 g_yhi[(size_t)MROWS * DI];      // scan output hi/lo (GEMM2 A)
__device__ __nv_bfloat16 g_ylo[(size_t)MROWS * DI];
__device__ __nv_bfloat16 g_woutT_hi[(size_t)DM * DI];    // W_out^T [1024][2048]
__device__ __nv_bfloat16 g_woutT_lo[(size_t)DM * DI];

// ---------------- fast math helpers ----------------
__device__ __forceinline__ float ex2a(float x) { float r; asm("ex2.approx.f32 %0, %1;" : "=f"(r) : "f"(x)); return r; }
__device__ __forceinline__ float lg2a(float x) { float r; asm("lg2.approx.f32 %0, %1;" : "=f"(r) : "f"(x)); return r; }
__device__ __forceinline__ float rcpa(float x) { float r; asm("rcp.approx.f32 %0, %1;" : "=f"(r) : "f"(x)); return r; }
#define LOG2E 1.44269504088896340736f
#define LN2   0.69314718055994530942f

__device__ __forceinline__ float silu_f(float v) {
    return v * rcpa(1.f + ex2a(-LOG2E * v));
}

// ---------------- cp.async helpers ----------------
__device__ __forceinline__ uint32_t smem_u32(const void* p) {
    uint32_t a;
    asm("{ .reg .u64 t; cvta.to.shared.u64 t, %1; cvt.u32.u64 %0, t; }" : "=r"(a) : "l"(p));
    return a;
}
__device__ __forceinline__ void cpasync16(uint32_t dst, const void* src) {
    asm volatile("cp.async.cg.shared.global [%0], [%1], 16;" :: "r"(dst), "l"(src));
}
__device__ __forceinline__ void cpasync_commit() { asm volatile("cp.async.commit_group;" ::: "memory"); }
__device__ __forceinline__ void cpasync_wait1() { asm volatile("cp.async.wait_group 1;" ::: "memory"); }
__device__ __forceinline__ void cpasync_wait0() { asm volatile("cp.async.wait_group 0;" ::: "memory"); }

// ---------------- bf16 hi/lo split helpers ----------------
__device__ __forceinline__ void split_bf16(float x, __nv_bfloat16& hi, __nv_bfloat16& lo) {
    hi = __float2bfloat16_rn(x);
    lo = __float2bfloat16_rn(x - __bfloat162float(hi));
}

// ---------------- WMMA bf16 split GEMM ----------------
// C[M,N] = A[M,K] @ Bt[N,K]^T with A,Bt given as bf16 hi/lo pairs, C fp32.
// C = Ahi*Bhi + Ahi*Blo + Alo*Bhi  (fp32 accumulate). Tile 128x128, BK=32.
// 256 threads, 8 warps (4m x 2n), warp tile 32x64. cp.async double-buffered.
static constexpr int GM_LDS = 40;                       // bf16 elems per smem row (80B)
static constexpr int GM_TILE = 128 * GM_LDS;            // elems per matrix per stage
static constexpr int GM_SMEM = 8 * GM_TILE * 2;         // bytes: 4 matrices x 2 stages

template<int M, int N, int K>
__global__ __launch_bounds__(256, 1) void mma_gemm(
    const __nv_bfloat16* __restrict__ Ahi, const __nv_bfloat16* __restrict__ Alo,
    const __nv_bfloat16* __restrict__ Bhi, const __nv_bfloat16* __restrict__ Blo,
    float* __restrict__ C)
{
    constexpr int BM = 128, BN = 128, BK = 32;
    extern __shared__ __nv_bfloat16 sm[];
    __nv_bfloat16* sAhi = sm;                 // [2][128][GM_LDS]
    __nv_bfloat16* sAlo = sm + 2 * GM_TILE;
    __nv_bfloat16* sBhi = sm + 4 * GM_TILE;
    __nv_bfloat16* sBlo = sm + 6 * GM_TILE;

    const int tid = threadIdx.x;
    const int wid = tid >> 5;
    const int m0 = blockIdx.y * BM;
    const int n0 = blockIdx.x * BN;
    const int wm = (wid >> 1) * 32;           // warp m offset
    const int wn = (wid & 1) * 64;            // warp n offset

    const uint32_t saAhi = smem_u32(sAhi);
    const uint32_t saAlo = smem_u32(sAlo);
    const uint32_t saBhi = smem_u32(sBhi);
    const uint32_t saBlo = smem_u32(sBlo);

    // chunk map: 512 16B-chunks per 128x32 tile; 2 per thread
    const int r0c = (tid * 2) >> 2, c0c = ((tid * 2) & 3) * 8;
    const int r1c = (tid * 2 + 1) >> 2, c1c = ((tid * 2 + 1) & 3) * 8;

    auto load_stage = [&](int t, int s) {
        const int kt = t * BK;
        const uint32_t d0 = (uint32_t)((s * BM + r0c) * GM_LDS + c0c) * 2;
        const uint32_t d1 = (uint32_t)((s * BM + r1c) * GM_LDS + c1c) * 2;
        const size_t a0 = (size_t)(m0 + r0c) * K + kt + c0c;
        const size_t a1 = (size_t)(m0 + r1c) * K + kt + c1c;
        const size_t b0 = (size_t)(n0 + r0c) * K + kt + c0c;
        const size_t b1 = (size_t)(n0 + r1c) * K + kt + c1c;
        cpasync16(saAhi + d0, Ahi + a0);  cpasync16(saAhi + d1, Ahi + a1);
        cpasync16(saAlo + d0, Alo + a0);  cpasync16(saAlo + d1, Alo + a1);
        cpasync16(saBhi + d0, Bhi + b0);  cpasync16(saBhi + d1, Bhi + b1);
        cpasync16(saBlo + d0, Blo + b0);  cpasync16(saBlo + d1, Blo + b1);
        cpasync_commit();
    };

    wmma::fragment<wmma::accumulator, 16, 16, 16, float> acc[2][4];
    #pragma unroll
    for (int i = 0; i < 2; ++i)
        #pragma unroll
        for (int j = 0; j < 4; ++j)
            wmma::fill_fragment(acc[i][j], 0.f);

    load_stage(0, 0);

    constexpr int T = K / BK;
    for (int t = 0; t < T; ++t) {
        const int s = t & 1;
        if (t + 1 < T) { load_stage(t + 1, s ^ 1); cpasync_wait1(); }
        else           { cpasync_wait0(); }
        __syncthreads();

        const __nv_bfloat16* pAhi = sAhi + s * GM_TILE;
        const __nv_bfloat16* pAlo = sAlo + s * GM_TILE;
        const __nv_bfloat16* pBhi = sBhi + s * GM_TILE;
        const __nv_bfloat16* pBlo = sBlo + s * GM_TILE;

        #pragma unroll
        for (int ks = 0; ks < BK; ks += 16) {
            wmma::fragment<wmma::matrix_a, 16, 16, 16, __nv_bfloat16, wmma::row_major> fah[2], fal[2];
            wmma::fragment<wmma::matrix_b, 16, 16, 16, __nv_bfloat16, wmma::col_major> fbh[4], fbl[4];
            #pragma unroll
            for (int i = 0; i < 2; ++i) {
                wmma::load_matrix_sync(fah[i], pAhi + (wm + i * 16) * GM_LDS + ks, GM_LDS);
                wmma::load_matrix_sync(fal[i], pAlo + (wm + i * 16) * GM_LDS + ks, GM_LDS);
            }
            #pragma unroll
            for (int j = 0; j < 4; ++j) {
                wmma::load_matrix_sync(fbh[j], pBhi + (wn + j * 16) * GM_LDS + ks, GM_LDS);
                wmma::load_matrix_sync(fbl[j], pBlo + (wn + j * 16) * GM_LDS + ks, GM_LDS);
            }
            #pragma unroll
            for (int i = 0; i < 2; ++i)
                #pragma unroll
                for (int j = 0; j < 4; ++j) {
                    wmma::mma_sync(acc[i][j], fah[i], fbh[j], acc[i][j]);
                    wmma::mma_sync(acc[i][j], fah[i], fbl[j], acc[i][j]);
                    wmma::mma_sync(acc[i][j], fal[i], fbh[j], acc[i][j]);
                }
        }
        __syncthreads();
    }

    #pragma unroll
    for (int i = 0; i < 2; ++i)
        #pragma unroll
        for (int j = 0; j < 4; ++j)
            wmma::store_matrix_sync(C + (size_t)(m0 + wm + i * 16) * N + n0 + wn + j * 16,
                                    acc[i][j], N, wmma::mem_row_major);
}

// ---------------- convert fp32 -> bf16 hi/lo (elementwise) ----------------
__global__ __launch_bounds__(256) void convert_kernel(
    const float* __restrict__ in, __nv_bfloat16* __restrict__ hi,
    __nv_bfloat16* __restrict__ lo, int n4)
{
    const int i = blockIdx.x * 256 + threadIdx.x;
    if (i >= n4) return;
    float4 v = ((const float4*)in)[i];
    __nv_bfloat16 h[4], l[4];
    split_bf16(v.x, h[0], l[0]); split_bf16(v.y, h[1], l[1]);
    split_bf16(v.z, h[2], l[2]); split_bf16(v.w, h[3], l[3]);
    ((uint2*)hi)[i] = *(uint2*)h;
    ((uint2*)lo)[i] = *(uint2*)l;
}

// ---------------- transpose + convert: in[R][C] fp32 -> outT[C][R] bf16 hi/lo ----------------
__global__ __launch_bounds__(256) void transpose_convert_kernel(
    const float* __restrict__ in, __nv_bfloat16* __restrict__ hiT,
    __nv_bfloat16* __restrict__ loT, int R, int C)
{
    __shared__ float t[32][33];
    const int tx = threadIdx.x & 31, ty = threadIdx.x >> 5;   // 32x8
    const int c0 = blockIdx.x * 32, r0 = blockIdx.y * 32;
    #pragma unroll
    for (int i = 0; i < 4; ++i)
        t[ty + i * 8][tx] = in[(size_t)(r0 + ty + i * 8) * C + c0 + tx];
    __syncthreads();
    #pragma unroll
    for (int i = 0; i < 4; ++i) {
        float v = t[tx][ty + i * 8];
        __nv_bfloat16 h, l;
        split_bf16(v, h, l);
        const size_t o = (size_t)(c0 + ty + i * 8) * R + r0 + tx;
        hiT[o] = h;
        loT[o] = l;
    }
}

// ---------------- depthwise causal conv (D_CONV=4) + SiLU ----------------
__global__ __launch_bounds__(256) void conv_silu_kernel(
    const float* __restrict__ conv_w, const float* __restrict__ conv_b)
{
    const int d  = blockIdx.x * 256 + threadIdx.x;
    const int l0 = blockIdx.y * 128;
    const int b  = blockIdx.z;

    const float w0 = conv_w[d * 4 + 0];
    const float w1 = conv_w[d * 4 + 1];
    const float w2 = conv_w[d * 4 + 2];
    const float w3 = conv_w[d * 4 + 3];
    const float bias = conv_b[d];

    const float* base = g_xz + ((size_t)b * LSEQ) * NXZ + d;
    float xm3 = (l0 >= 3) ? base[(size_t)(l0 - 3) * NXZ] : 0.f;
    float xm2 = (l0 >= 2) ? base[(size_t)(l0 - 2) * NXZ] : 0.f;
    float xm1 = (l0 >= 1) ? base[(size_t)(l0 - 1) * NXZ] : 0.f;

    float* outp = g_xs + ((size_t)b * LSEQ + l0) * DI + d;
    #pragma unroll 4
    for (int i = 0; i < 128; ++i) {
        float xl = base[(size_t)(l0 + i) * NXZ];
        float v = bias + w0 * xm3 + w1 * xm2 + w2 * xm1 + w3 * xl;
        outp[(size_t)i * DI] = silu_f(v);
        xm3 = xm2; xm2 = xm1; xm1 = xl;
    }
}

// ---------------- x_dbl = xs @ W_x  (N=33) ----------------
__global__ __launch_bounds__(128) void dbl_kernel(const float* __restrict__ W_x)
{
    __shared__ float xs_s[64][33];
    __shared__ float wx_s[32][33];
    const int tid = threadIdx.x;
    const int r = tid & 63;
    const int jh = tid >> 6;
    const int rows0 = blockIdx.x * 64;

    float acc[17];
    #pragma unroll
    for (int jj = 0; jj < 17; ++jj) acc[jj] = 0.f;

    for (int kt = 0; kt < DI; kt += 32) {
        __syncthreads();
        #pragma unroll
        for (int i = 0; i < 16; ++i) {
            int id = tid + i * 128;
            int rr = id >> 5, kk = id & 31;
            xs_s[rr][kk] = g_xs[(size_t)(rows0 + rr) * DI + kt + kk];
        }
        for (int idx = tid; idx < 32 * 33; idx += 128) {
            int kk = idx / 33, j = idx % 33;
            wx_s[kk][j] = W_x[(size_t)(kt + kk) * NDBL + j];
        }
        __syncthreads();
        #pragma unroll
        for (int k = 0; k < 32; ++k) {
            float xv = xs_s[r][k];
            const float* wrow = &wx_s[k][jh * 17];
            #pragma unroll
            for (int jj = 0; jj < 16; ++jj)
                acc[jj] = fmaf(xv, wrow[jj], acc[jj]);
            if (jh == 0)
                acc[16] = fmaf(xv, wrow[16], acc[16]);
        }
    }
    const int nj = 17 - jh;
    const int jbase = jh * 17;
    for (int jj = 0; jj < nj; ++jj)
        g_dbl[(size_t)(rows0 + r) * NDBL + jbase + jj] = acc[jj];
}

// ---------------- delta = softplus(draw * w_dt + b_dt) ----------------
__global__ __launch_bounds__(256) void delta_kernel(
    const float* __restrict__ w_dt, const float* __restrict__ b_dt)
{
    const int d = blockIdx.x * 256 + threadIdx.x;
    const int row = blockIdx.y;
    float draw = g_dbl[(size_t)row * NDBL];
    float xv = fmaf(draw, w_dt[d], b_dt[d]);
    float t = ex2a(-LOG2E * fabsf(xv));
    float sp = fmaxf(xv, 0.f) + LN2 * lg2a(1.f + t);
    g_delta[(size_t)row * DI + d] = sp;
}

// ---------------- selective scan + output gating (writes y hi/lo bf16) ----------------
__global__ __launch_bounds__(128) void scan_kernel(
    const float* __restrict__ A_log, const float* __restrict__ Dw)
{
    const int b = blockIdx.y;
    const int d0 = blockIdx.x * 64;
    const int tid = threadIdx.x;
    const int ch = tid >> 1;
    const int half = tid & 1;
    const int d = d0 + ch;
    const int row0 = b * LSEQ;

    float cn[8];
    #pragma unroll
    for (int j = 0; j < 8; ++j)
        cn[j] = -__expf(A_log[(size_t)d * DS + half * 8 + j]) * LOG2E;
    const float Dv = Dw[d];

    float h[8];
    #pragma unroll
    for (int j = 0; j < 8; ++j) h[j] = 0.f;

    __shared__ float sB[32][16];
    __shared__ float sC[32][16];

    for (int lc = 0; lc < LSEQ; lc += 32) {
        __syncthreads();
        #pragma unroll
        for (int i = 0; i < 8; ++i) {
            int id = tid + i * 128;
            int ll = id >> 5;
            int cc = id & 31;
            float v = g_dbl[(size_t)(row0 + lc + ll) * NDBL + 1 + cc];
            if (cc < 16) sB[ll][cc] = v; else sC[ll][cc - 16] = v;
        }
        __syncthreads();

        for (int i = 0; i < 32; ++i) {
            const int l = lc + i;
            const size_t idx = (size_t)(row0 + l) * DI + d;
            float dt = g_delta[idx];
            float xv = g_xs[idx];
            float dtx = dt * xv;
            float yacc = 0.f;
            const float* bp = &sB[i][half * 8];
            const float* cp = &sC[i][half * 8];
            #pragma unroll
            for (int j = 0; j < 8; ++j) {
                float a = ex2a(dt * cn[j]);
                float t = dtx * bp[j];
                h[j] = fmaf(a, h[j], t);
                yacc = fmaf(h[j], cp[j], yacc);
            }
            yacc += __shfl_xor_sync(0xffffffffu, yacc, 1);
            if (half == 0) {
                float zv = g_xz[(size_t)(row0 + l) * NXZ + DI + d];
                float out = (yacc + xv * Dv) * silu_f(zv);
                __nv_bfloat16 hh, ll2;
                split_bf16(out, hh, ll2);
                g_yhi[idx] = hh;
                g_ylo[idx] = ll2;
            }
        }
    }
}

// ---------------- launch ----------------
extern "C" void kernel_launch(void* const* d_in, const int* in_sizes, int n_in,
                              void* d_out, int out_size)
{
    const float* x      = (const float*)d_in[0];
    const float* W_in   = (const float*)d_in[1];
    const float* conv_w = (const float*)d_in[2];
    const float* conv_b = (const float*)d_in[3];
    const float* W_x    = (const float*)d_in[4];
    const float* w_dt   = (const float*)d_in[5];
    const float* b_dt   = (const float*)d_in[6];
    const float* A_log  = (const float*)d_in[7];
    const float* Dw     = (const float*)d_in[8];
    const float* W_out  = (const float*)d_in[9];
    float* out = (float*)d_out;

    static bool attr_set = false;
    if (!attr_set) {
        cudaFuncSetAttribute(mma_gemm<MROWS, NXZ, DM>,
                             cudaFuncAttributeMaxDynamicSharedMemorySize, GM_SMEM);
        cudaFuncSetAttribute(mma_gemm<MROWS, DM, DI>,
                             cudaFuncAttributeMaxDynamicSharedMemorySize, GM_SMEM);
        attr_set = true;
    }

    __nv_bfloat16 *xhi, *xlo, *wih, *wil, *yhi, *ylo, *woh, *wol;
    float *xz, *ydummy;
    cudaGetSymbolAddress((void**)&xhi, g_xhi);
    cudaGetSymbolAddress((void**)&xlo, g_xlo);
    cudaGetSymbolAddress((void**)&wih, g_winT_hi);
    cudaGetSymbolAddress((void**)&wil, g_winT_lo);
    cudaGetSymbolAddress((void**)&yhi, g_yhi);
    cudaGetSymbolAddress((void**)&ylo, g_ylo);
    cudaGetSymbolAddress((void**)&woh, g_woutT_hi);
    cudaGetSymbolAddress((void**)&wol, g_woutT_lo);
    cudaGetSymbolAddress((void**)&xz, g_xz);
    (void)ydummy;

    // 0) operand preparation (bf16 hi/lo)
    convert_kernel<<<(MROWS * DM / 4 + 255) / 256, 256>>>(x, xhi, xlo, MROWS * DM / 4);
    transpose_convert_kernel<<<dim3(NXZ / 32, DM / 32), 256>>>(W_in, wih, wil, DM, NXZ);
    transpose_convert_kernel<<<dim3(DM / 32, DI / 32), 256>>>(W_out, woh, wol, DI, DM);

    // 1) xz = x @ W_in  (bf16-split WMMA)
    mma_gemm<MROWS, NXZ, DM><<<dim3(NXZ / 128, MROWS / 128), 256, GM_SMEM>>>(
        xhi, xlo, wih, wil, xz);
    // 2) xs = silu(conv(xc))
    conv_silu_kernel<<<dim3(DI / 256, LSEQ / 128, BSZ), 256>>>(conv_w, conv_b);
    // 3) x_dbl = xs @ W_x
    dbl_kernel<<<MROWS / 64, 128>>>(W_x);
    // 4) delta
    delta_kernel<<<dim3(DI / 256, MROWS), 256>>>(w_dt, b_dt);
    // 5) selective scan + gating -> y hi/lo
    scan_kernel<<<dim3(DI / 64, BSZ), 128>>>(A_log, Dw);
    // 6) out = y @ W_out  (bf16-split WMMA)
    mma_gemm<MROWS, DM, DI><<<dim3(DM / 128, MROWS / 128), 256, GM_SMEM>>>(
        yhi, ylo, woh, wol, out);
}

// round 4
// speedup vs baseline: 2.8405x; 2.3705x over previous
#include <cuda_runtime.h>
#include <cuda_bf16.h>
#include <mma.h>
#include <cstdint>

using namespace nvcuda;

// ---------------- Problem constants ----------------
#define BSZ     4
#define LSEQ    2048
#define DM      1024
#define DI      2048
#define DS      16
#define MROWS   (BSZ*LSEQ)      // 8192
#define NXZ     (2*DI)          // 4096
#define NDBL    (1 + 2*DS)      // 33
#define NC      16              // scan chunks
#define LC      (LSEQ/NC)       // 128 steps per chunk

// ---------------- Scratch (device globals; no allocation allowed) ----------------
__device__ float g_xz[(size_t)MROWS * NXZ];          // [row][0..2047]=xc, [2048..4095]=z
__device__ float g_xs[(size_t)MROWS * DI];           // silu(conv(xc))
__device__ float g_dbl[(size_t)MROWS * NDBL];        // [draw | B(16) | C(16)]
__device__ float g_tc[(size_t)MROWS * DI];           // inclusive dt-cumsum within chunk
__device__ float g_y[(size_t)MROWS * DI];            // chunk-local scan output y_loc
__device__ float g_S[(size_t)BSZ * NC * DI * DS];    // chunk-final local states
__device__ float g_Hin[(size_t)BSZ * NC * DI * DS];  // incoming state per chunk

__device__ __nv_bfloat16 g_xhi[(size_t)MROWS * DM];      // x hi/lo (GEMM1 A)
__device__ __nv_bfloat16 g_xlo[(size_t)MROWS * DM];
__device__ __nv_bfloat16 g_winT_hi[(size_t)NXZ * DM];    // W_in^T [4096][1024]
__device__ __nv_bfloat16 g_winT_lo[(size_t)NXZ * DM];
__device__ __nv_bfloat16 g_yhi[(size_t)MROWS * DI];      // gated output hi/lo (GEMM2 A)
__device__ __nv_bfloat16 g_ylo[(size_t)MROWS * DI];
__device__ __nv_bfloat16 g_woutT_hi[(size_t)DM * DI];    // W_out^T [1024][2048]
__device__ __nv_bfloat16 g_woutT_lo[(size_t)DM * DI];

// ---------------- fast math helpers ----------------
__device__ __forceinline__ float ex2a(float x) { float r; asm("ex2.approx.f32 %0, %1;" : "=f"(r) : "f"(x)); return r; }
__device__ __forceinline__ float lg2a(float x) { float r; asm("lg2.approx.f32 %0, %1;" : "=f"(r) : "f"(x)); return r; }
__device__ __forceinline__ float rcpa(float x) { float r; asm("rcp.approx.f32 %0, %1;" : "=f"(r) : "f"(x)); return r; }
#define LOG2E 1.44269504088896340736f
#define LN2   0.69314718055994530942f

__device__ __forceinline__ float silu_f(float v) {
    return v * rcpa(1.f + ex2a(-LOG2E * v));
}
__device__ __forceinline__ float softplus_f(float v) {
    float t = ex2a(-LOG2E * fabsf(v));
    return fmaxf(v, 0.f) + LN2 * lg2a(1.f + t);
}

// ---------------- cp.async helpers ----------------
__device__ __forceinline__ uint32_t smem_u32(const void* p) {
    uint32_t a;
    asm("{ .reg .u64 t; cvta.to.shared.u64 t, %1; cvt.u32.u64 %0, t; }" : "=r"(a) : "l"(p));
    return a;
}
__device__ __forceinline__ void cpasync16(uint32_t dst, const void* src) {
    asm volatile("cp.async.cg.shared.global [%0], [%1], 16;" :: "r"(dst), "l"(src));
}
__device__ __forceinline__ void cpasync_commit() { asm volatile("cp.async.commit_group;" ::: "memory"); }
__device__ __forceinline__ void cpasync_wait1() { asm volatile("cp.async.wait_group 1;" ::: "memory"); }
__device__ __forceinline__ void cpasync_wait0() { asm volatile("cp.async.wait_group 0;" ::: "memory"); }

// ---------------- bf16 hi/lo split helpers ----------------
__device__ __forceinline__ void split_bf16(float x, __nv_bfloat16& hi, __nv_bfloat16& lo) {
    hi = __float2bfloat16_rn(x);
    lo = __float2bfloat16_rn(x - __bfloat162float(hi));
}

// ---------------- WMMA bf16 split GEMM ----------------
// C[M,N] = A @ Bt^T, A/Bt bf16 hi/lo, fp32 acc. C = AhiBhi + AhiBlo + AloBhi.
// Tile 128x128, BK=32. 128 threads, 4 warps, 64x64 warp tiles. 2 CTAs/SM.
static constexpr int GM_LDS = 40;                       // bf16 elems per smem row (80B)
static constexpr int GM_TILE = 128 * GM_LDS;            // elems per matrix per stage
static constexpr int GM_SMEM = 8 * GM_TILE * 2;         // bytes: 4 matrices x 2 stages

template<int M, int N, int K>
__global__ __launch_bounds__(128) void mma_gemm(
    const __nv_bfloat16* __restrict__ Ahi, const __nv_bfloat16* __restrict__ Alo,
    const __nv_bfloat16* __restrict__ Bhi, const __nv_bfloat16* __restrict__ Blo,
    float* __restrict__ C)
{
    constexpr int BM = 128, BN = 128, BK = 32;
    extern __shared__ __nv_bfloat16 sm[];
    __nv_bfloat16* sAhi = sm;                 // [2][128][GM_LDS]
    __nv_bfloat16* sAlo = sm + 2 * GM_TILE;
    __nv_bfloat16* sBhi = sm + 4 * GM_TILE;
    __nv_bfloat16* sBlo = sm + 6 * GM_TILE;

    const int tid = threadIdx.x;
    const int wid = tid >> 5;
    const int m0 = blockIdx.y * BM;
    const int n0 = blockIdx.x * BN;
    const int wm = (wid >> 1) * 64;           // warp m offset
    const int wn = (wid & 1) * 64;            // warp n offset

    const uint32_t saAhi = smem_u32(sAhi);
    const uint32_t saAlo = smem_u32(sAlo);
    const uint32_t saBhi = smem_u32(sBhi);
    const uint32_t saBlo = smem_u32(sBlo);

    // chunk map: 512 16B-chunks per 128x32 tile; 4 per thread
    int rc[4], cc[4];
    #pragma unroll
    for (int i = 0; i < 4; ++i) {
        int q = tid + i * 128;
        rc[i] = q >> 2;
        cc[i] = (q & 3) * 8;
    }

    auto load_stage = [&](int t, int s) {
        const int kt = t * BK;
        #pragma unroll
        for (int i = 0; i < 4; ++i) {
            const uint32_t d = (uint32_t)((s * BM + rc[i]) * GM_LDS + cc[i]) * 2;
            const size_t a = (size_t)(m0 + rc[i]) * K + kt + cc[i];
            const size_t b = (size_t)(n0 + rc[i]) * K + kt + cc[i];
            cpasync16(saAhi + d, Ahi + a);
            cpasync16(saAlo + d, Alo + a);
            cpasync16(saBhi + d, Bhi + b);
            cpasync16(saBlo + d, Blo + b);
        }
        cpasync_commit();
    };

    wmma::fragment<wmma::accumulator, 16, 16, 16, float> acc[4][4];
    #pragma unroll
    for (int i = 0; i < 4; ++i)
        #pragma unroll
        for (int j = 0; j < 4; ++j)
            wmma::fill_fragment(acc[i][j], 0.f);

    load_stage(0, 0);

    constexpr int T = K / BK;
    for (int t = 0; t < T; ++t) {
        const int s = t & 1;
        if (t + 1 < T) { load_stage(t + 1, s ^ 1); cpasync_wait1(); }
        else           { cpasync_wait0(); }
        __syncthreads();

        const __nv_bfloat16* pAhi = sAhi + s * GM_TILE;
        const __nv_bfloat16* pAlo = sAlo + s * GM_TILE;
        const __nv_bfloat16* pBhi = sBhi + s * GM_TILE;
        const __nv_bfloat16* pBlo = sBlo + s * GM_TILE;

        #pragma unroll
        for (int ks = 0; ks < BK; ks += 16) {
            wmma::fragment<wmma::matrix_b, 16, 16, 16, __nv_bfloat16, wmma::col_major> fbh[4], fbl[4];
            #pragma unroll
            for (int j = 0; j < 4; ++j) {
                wmma::load_matrix_sync(fbh[j], pBhi + (wn + j * 16) * GM_LDS + ks, GM_LDS);
                wmma::load_matrix_sync(fbl[j], pBlo + (wn + j * 16) * GM_LDS + ks, GM_LDS);
            }
            #pragma unroll
            for (int i = 0; i < 4; ++i) {
                wmma::fragment<wmma::matrix_a, 16, 16, 16, __nv_bfloat16, wmma::row_major> fah, fal;
                wmma::load_matrix_sync(fah, pAhi + (wm + i * 16) * GM_LDS + ks, GM_LDS);
                wmma::load_matrix_sync(fal, pAlo + (wm + i * 16) * GM_LDS + ks, GM_LDS);
                #pragma unroll
                for (int j = 0; j < 4; ++j) {
                    wmma::mma_sync(acc[i][j], fah, fbh[j], acc[i][j]);
                    wmma::mma_sync(acc[i][j], fah, fbl[j], acc[i][j]);
                    wmma::mma_sync(acc[i][j], fal, fbh[j], acc[i][j]);
                }
            }
        }
        __syncthreads();
    }

    #pragma unroll
    for (int i = 0; i < 4; ++i)
        #pragma unroll
        for (int j = 0; j < 4; ++j)
            wmma::store_matrix_sync(C + (size_t)(m0 + wm + i * 16) * N + n0 + wn + j * 16,
                                    acc[i][j], N, wmma::mem_row_major);
}

// ---------------- convert fp32 -> bf16 hi/lo ----------------
__global__ __launch_bounds__(256) void convert_kernel(
    const float* __restrict__ in, __nv_bfloat16* __restrict__ hi,
    __nv_bfloat16* __restrict__ lo, int n4)
{
    const int i = blockIdx.x * 256 + threadIdx.x;
    if (i >= n4) return;
    float4 v = ((const float4*)in)[i];
    __nv_bfloat16 h[4], l[4];
    split_bf16(v.x, h[0], l[0]); split_bf16(v.y, h[1], l[1]);
    split_bf16(v.z, h[2], l[2]); split_bf16(v.w, h[3], l[3]);
    ((uint2*)hi)[i] = *(uint2*)h;
    ((uint2*)lo)[i] = *(uint2*)l;
}

// ---------------- transpose + convert ----------------
__global__ __launch_bounds__(256) void transpose_convert_kernel(
    const float* __restrict__ in, __nv_bfloat16* __restrict__ hiT,
    __nv_bfloat16* __restrict__ loT, int R, int C)
{
    __shared__ float t[32][33];
    const int tx = threadIdx.x & 31, ty = threadIdx.x >> 5;
    const int c0 = blockIdx.x * 32, r0 = blockIdx.y * 32;
    #pragma unroll
    for (int i = 0; i < 4; ++i)
        t[ty + i * 8][tx] = in[(size_t)(r0 + ty + i * 8) * C + c0 + tx];
    __syncthreads();
    #pragma unroll
    for (int i = 0; i < 4; ++i) {
        float v = t[tx][ty + i * 8];
        __nv_bfloat16 h, l;
        split_bf16(v, h, l);
        const size_t o = (size_t)(c0 + ty + i * 8) * R + r0 + tx;
        hiT[o] = h;
        loT[o] = l;
    }
}

// ---------------- depthwise causal conv (D_CONV=4) + SiLU ----------------
__global__ __launch_bounds__(256) void conv_silu_kernel(
    const float* __restrict__ conv_w, const float* __restrict__ conv_b)
{
    const int d  = blockIdx.x * 256 + threadIdx.x;
    const int l0 = blockIdx.y * 128;
    const int b  = blockIdx.z;

    const float w0 = conv_w[d * 4 + 0];
    const float w1 = conv_w[d * 4 + 1];
    const float w2 = conv_w[d * 4 + 2];
    const float w3 = conv_w[d * 4 + 3];
    const float bias = conv_b[d];

    const float* base = g_xz + ((size_t)b * LSEQ) * NXZ + d;
    float xm3 = (l0 >= 3) ? base[(size_t)(l0 - 3) * NXZ] : 0.f;
    float xm2 = (l0 >= 2) ? base[(size_t)(l0 - 2) * NXZ] : 0.f;
    float xm1 = (l0 >= 1) ? base[(size_t)(l0 - 1) * NXZ] : 0.f;

    float* outp = g_xs + ((size_t)b * LSEQ + l0) * DI + d;
    #pragma unroll 4
    for (int i = 0; i < 128; ++i) {
        float xl = base[(size_t)(l0 + i) * NXZ];
        float v = bias + w0 * xm3 + w1 * xm2 + w2 * xm1 + w3 * xl;
        outp[(size_t)i * DI] = silu_f(v);
        xm3 = xm2; xm2 = xm1; xm1 = xl;
    }
}

// ---------------- x_dbl = xs @ W_x  (N=33) ----------------
__global__ __launch_bounds__(128) void dbl_kernel(const float* __restrict__ W_x)
{
    __shared__ float xs_s[64][33];
    __shared__ float wx_s[32][33];
    const int tid = threadIdx.x;
    const int r = tid & 63;
    const int jh = tid >> 6;
    const int rows0 = blockIdx.x * 64;

    float acc[17];
    #pragma unroll
    for (int jj = 0; jj < 17; ++jj) acc[jj] = 0.f;

    for (int kt = 0; kt < DI; kt += 32) {
        __syncthreads();
        #pragma unroll
        for (int i = 0; i < 16; ++i) {
            int id = tid + i * 128;
            int rr = id >> 5, kk = id & 31;
            xs_s[rr][kk] = g_xs[(size_t)(rows0 + rr) * DI + kt + kk];
        }
        for (int idx = tid; idx < 32 * 33; idx += 128) {
            int kk = idx / 33, j = idx % 33;
            wx_s[kk][j] = W_x[(size_t)(kt + kk) * NDBL + j];
        }
        __syncthreads();
        #pragma unroll
        for (int k = 0; k < 32; ++k) {
            float xv = xs_s[r][k];
            const float* wrow = &wx_s[k][jh * 17];
            #pragma unroll
            for (int jj = 0; jj < 16; ++jj)
                acc[jj] = fmaf(xv, wrow[jj], acc[jj]);
            if (jh == 0)
                acc[16] = fmaf(xv, wrow[16], acc[16]);
        }
    }
    const int nj = 17 - jh;
    const int jbase = jh * 17;
    for (int jj = 0; jj < nj; ++jj)
        g_dbl[(size_t)(rows0 + r) * NDBL + jbase + jj] = acc[jj];
}

// ---------------- scan pass A: chunk-local scan ----------------
// Block: 128 threads = 64 channels x 2 halves (8 states each).
// Grid: (DI/64, NC, BSZ). Computes dt=softplus inline, writes y_loc, Tcum, S.
__global__ __launch_bounds__(128) void scan_local_kernel(
    const float* __restrict__ A_log,
    const float* __restrict__ w_dt, const float* __restrict__ b_dt)
{
    const int b = blockIdx.z;
    const int c = blockIdx.y;
    const int d0 = blockIdx.x * 64;
    const int tid = threadIdx.x;
    const int ch = tid >> 1;
    const int half = tid & 1;
    const int d = d0 + ch;
    const int row0 = b * LSEQ + c * LC;

    float cnE[8];
    #pragma unroll
    for (int j = 0; j < 8; ++j)
        cnE[j] = -__expf(A_log[(size_t)d * DS + half * 8 + j]) * LOG2E;
    const float wdt = w_dt[d];
    const float bdt = b_dt[d];

    float h[8];
    #pragma unroll
    for (int j = 0; j < 8; ++j) h[j] = 0.f;
    float Tc = 0.f;

    __shared__ float sD[32];
    __shared__ float sB[32][16];
    __shared__ float sC[32][16];

    for (int lc = 0; lc < LC; lc += 32) {
        __syncthreads();
        #pragma unroll
        for (int i = 0; i < 9; ++i) {
            int id = tid + i * 128;
            if (id < 32 * 33) {
                int ll = id / 33;
                int cc = id - ll * 33;
                float v = g_dbl[(size_t)(row0 + lc + ll) * NDBL + cc];
                if (cc == 0) sD[ll] = v;
                else if (cc < 17) sB[ll][cc - 1] = v;
                else sC[ll][cc - 17] = v;
            }
        }
        __syncthreads();

        for (int i = 0; i < 32; ++i) {
            const size_t idx = (size_t)(row0 + lc + i) * DI + d;
            float dt = softplus_f(fmaf(sD[i], wdt, bdt));
            Tc += dt;
            float xs = g_xs[idx];
            float dtx = dt * xs;
            float yacc = 0.f;
            const float* bp = &sB[i][half * 8];
            const float* cp = &sC[i][half * 8];
            #pragma unroll
            for (int j = 0; j < 8; ++j) {
                float a = ex2a(dt * cnE[j]);
                h[j] = fmaf(a, h[j], dtx * bp[j]);
                yacc = fmaf(h[j], cp[j], yacc);
            }
            yacc += __shfl_xor_sync(0xffffffffu, yacc, 1);
            if (half == 0) {
                g_y[idx] = yacc;
                g_tc[idx] = Tc;
            }
        }
    }

    #pragma unroll
    for (int j = 0; j < 8; ++j)
        g_S[((((size_t)b * NC + c) * DI) + d) * DS + half * 8 + j] = h[j];
}

// ---------------- scan pass B: combine chunk states ----------------
__global__ __launch_bounds__(256) void scan_combine_kernel(const float* __restrict__ A_log)
{
    const int t = blockIdx.x * 256 + threadIdx.x;     // 131072 total
    const int n = t & 15;
    const int d = (t >> 4) & (DI - 1);
    const int b = t >> 15;
    const float An = -__expf(A_log[(size_t)d * DS + n]) * LOG2E;
    float H = 0.f;
    #pragma unroll
    for (int c = 0; c < NC; ++c) {
        const size_t sidx = (((size_t)b * NC + c) * DI + d) * DS + n;
        g_Hin[sidx] = H;
        float Ds = g_tc[(size_t)(b * LSEQ + c * LC + LC - 1) * DI + d];
        float S = g_S[sidx];
        H = fmaf(ex2a(An * Ds), H, S);
    }
}

// ---------------- scan pass C: add cross-chunk correction + gate ----------------
__global__ __launch_bounds__(128) void scan_final_kernel(
    const float* __restrict__ A_log, const float* __restrict__ Dw)
{
    const int b = blockIdx.z;
    const int c = blockIdx.y;
    const int d0 = blockIdx.x * 64;
    const int tid = threadIdx.x;
    const int ch = tid >> 1;
    const int half = tid & 1;
    const int d = d0 + ch;
    const int row0 = b * LSEQ + c * LC;

    float cnE[8], Hn[8];
    #pragma unroll
    for (int j = 0; j < 8; ++j) {
        cnE[j] = -__expf(A_log[(size_t)d * DS + half * 8 + j]) * LOG2E;
        Hn[j] = g_Hin[(((size_t)b * NC + c) * DI + d) * DS + half * 8 + j];
    }
    const float Dv = Dw[d];

    __shared__ float sC2[32][16];

    for (int lc = 0; lc < LC; lc += 32) {
        __syncthreads();
        #pragma unroll
        for (int i = 0; i < 4; ++i) {
            int id = tid + i * 128;     // 512 = 32x16
            int ll = id >> 4;
            int cc = id & 15;
            sC2[ll][cc] = g_dbl[(size_t)(row0 + lc + ll) * NDBL + 17 + cc];
        }
        __syncthreads();

        for (int i = 0; i < 32; ++i) {
            const size_t idx = (size_t)(row0 + lc + i) * DI + d;
            const float Tc = g_tc[idx];
            float corr = 0.f;
            const float* cp = &sC2[i][half * 8];
            #pragma unroll
            for (int j = 0; j < 8; ++j)
                corr = fmaf(cp[j] * Hn[j], ex2a(cnE[j] * Tc), corr);
            corr += __shfl_xor_sync(0xffffffffu, corr, 1);
            if (half == 0) {
                float y = g_y[idx] + corr;
                float xs = g_xs[idx];
                float zv = g_xz[(size_t)(row0 + lc + i) * NXZ + DI + d];
                float out = (y + xs * Dv) * silu_f(zv);
                __nv_bfloat16 hh, ll2;
                split_bf16(out, hh, ll2);
                g_yhi[idx] = hh;
                g_ylo[idx] = ll2;
            }
        }
    }
}

// ---------------- launch ----------------
extern "C" void kernel_launch(void* const* d_in, const int* in_sizes, int n_in,
                              void* d_out, int out_size)
{
    const float* x      = (const float*)d_in[0];
    const float* W_in   = (const float*)d_in[1];
    const float* conv_w = (const float*)d_in[2];
    const float* conv_b = (const float*)d_in[3];
    const float* W_x    = (const float*)d_in[4];
    const float* w_dt   = (const float*)d_in[5];
    const float* b_dt   = (const float*)d_in[6];
    const float* A_log  = (const float*)d_in[7];
    const float* Dw     = (const float*)d_in[8];
    const float* W_out  = (const float*)d_in[9];
    float* out = (float*)d_out;

    static bool attr_set = false;
    if (!attr_set) {
        cudaFuncSetAttribute(mma_gemm<MROWS, NXZ, DM>,
                             cudaFuncAttributeMaxDynamicSharedMemorySize, GM_SMEM);
        cudaFuncSetAttribute(mma_gemm<MROWS, DM, DI>,
                             cudaFuncAttributeMaxDynamicSharedMemorySize, GM_SMEM);
        attr_set = true;
    }

    __nv_bfloat16 *xhi, *xlo, *wih, *wil, *yhi, *ylo, *woh, *wol;
    float *xz;
    cudaGetSymbolAddress((void**)&xhi, g_xhi);
    cudaGetSymbolAddress((void**)&xlo, g_xlo);
    cudaGetSymbolAddress((void**)&wih, g_winT_hi);
    cudaGetSymbolAddress((void**)&wil, g_winT_lo);
    cudaGetSymbolAddress((void**)&yhi, g_yhi);
    cudaGetSymbolAddress((void**)&ylo, g_ylo);
    cudaGetSymbolAddress((void**)&woh, g_woutT_hi);
    cudaGetSymbolAddress((void**)&wol, g_woutT_lo);
    cudaGetSymbolAddress((void**)&xz, g_xz);

    // 0) operand preparation (bf16 hi/lo)
    convert_kernel<<<(MROWS * DM / 4 + 255) / 256, 256>>>(x, xhi, xlo, MROWS * DM / 4);
    transpose_convert_kernel<<<dim3(NXZ / 32, DM / 32), 256>>>(W_in, wih, wil, DM, NXZ);
    transpose_convert_kernel<<<dim3(DM / 32, DI / 32), 256>>>(W_out, woh, wol, DI, DM);

    // 1) xz = x @ W_in  (bf16-split WMMA)
    mma_gemm<MROWS, NXZ, DM><<<dim3(NXZ / 128, MROWS / 128), 128, GM_SMEM>>>(
        xhi, xlo, wih, wil, xz);
    // 2) xs = silu(conv(xc))
    conv_silu_kernel<<<dim3(DI / 256, LSEQ / 128, BSZ), 256>>>(conv_w, conv_b);
    // 3) x_dbl = xs @ W_x
    dbl_kernel<<<MROWS / 64, 128>>>(W_x);
    // 4) chunked scan: local / combine / finalize (softplus fused into A)
    scan_local_kernel<<<dim3(DI / 64, NC, BSZ), 128>>>(A_log, w_dt, b_dt);
    scan_combine_kernel<<<(BSZ * DI * DS) / 256, 256>>>(A_log);
    scan_final_kernel<<<dim3(DI / 64, NC, BSZ), 128>>>(A_log, Dw);
    // 5) out = y @ W_out  (bf16-split WMMA)
    mma_gemm<MROWS, DM, DI><<<dim3(DM / 128, MROWS / 128), 128, GM_SMEM>>>(
        yhi, ylo, woh, wol, out);
}